// round 5
// baseline (speedup 1.0000x reference)
#include <cuda_runtime.h>
#include <math.h>

// Problem constants (shapes fixed by the dataset)
#define F_IN  512
#define HID   128
#define NCLS  64
#define MAX_N 131072
#define MAX_E 2097152

// ---------------- static device scratch (no allocations allowed) ----------------
__device__ __align__(16) float d_gbuf[(size_t)MAX_N * HID];  // 67 MB
__device__ __align__(16) float d_ybuf[(size_t)MAX_N * HID];  // 67 MB
__device__ float d_dinv[MAX_N];
__device__ int   d_deg[MAX_N];
__device__ int   d_off[MAX_N + 1];
__device__ int   d_cur[MAX_N];
__device__ int   d_csr[MAX_E];
__device__ int   d_bsum[256];
__device__ int   d_boff[256];

// ---------------- degree / dinv ----------------
__global__ void k_zero(int Nn) {
    int i = blockIdx.x * blockDim.x + threadIdx.x;
    if (i < Nn) { d_deg[i] = 0; d_cur[i] = 0; }
}

__global__ void k_count(const int* __restrict__ dst, int Ee) {
    int i = blockIdx.x * blockDim.x + threadIdx.x;
    if (i < Ee) atomicAdd(&d_deg[dst[i]], 1);
}

__global__ void k_dinv(int Nn) {
    int i = blockIdx.x * blockDim.x + threadIdx.x;
    if (i < Nn) d_dinv[i] = rsqrtf((float)d_deg[i] + 1.0f);  // +1 self loop
}

// ---------------- exclusive scan of d_deg -> d_off (3 kernels) ----------------
__global__ void k_scan1(int Nn) {
    __shared__ int sh[1024];
    int t = threadIdx.x;
    int i = blockIdx.x * 1024 + t;
    int v = (i < Nn) ? d_deg[i] : 0;
    sh[t] = v;
    __syncthreads();
    for (int s = 1; s < 1024; s <<= 1) {
        int x = (t >= s) ? sh[t - s] : 0;
        __syncthreads();
        sh[t] += x;
        __syncthreads();
    }
    if (i < Nn) d_off[i] = sh[t] - v;  // exclusive
    if (t == 1023) d_bsum[blockIdx.x] = sh[1023];
}

__global__ void k_scan2(int nb) {
    int run = 0;
    for (int b = 0; b < nb; b++) { d_boff[b] = run; run += d_bsum[b]; }
}

__global__ void k_scan3(int Nn, int Ee) {
    int i = blockIdx.x * 1024 + threadIdx.x;
    if (i < Nn) d_off[i] += d_boff[blockIdx.x];
    if (i == 0) d_off[Nn] = Ee;
}

__global__ void k_scatter(const int* __restrict__ src, const int* __restrict__ dst, int Ee) {
    int i = blockIdx.x * blockDim.x + threadIdx.x;
    if (i < Ee) {
        int d = dst[i];
        int p = d_off[d] + atomicAdd(&d_cur[d], 1);
        d_csr[p] = src[i];
    }
}

// ---------------- SGEMM: C[M,128] = A[M,K] @ W[K,128] (+bias)(*dinv)(relu) ----------------
// BM=128, BN=128, BK=16, 256 threads, 8x8 microtile.
__global__ __launch_bounds__(256) void k_sgemm(
    const float* __restrict__ A, const float* __restrict__ W,
    const float* __restrict__ bias, int useDinv, int doRelu,
    float* __restrict__ Cc, int M, int K)
{
    __shared__ float As[16][128];
    __shared__ float Ws[16][128];

    int tid = threadIdx.x;
    int tx = tid & 15;          // col group (8 cols each)
    int ty = tid >> 4;          // row group (8 rows each)
    int row0 = blockIdx.x * 128;

    float acc[8][8];
#pragma unroll
    for (int i = 0; i < 8; i++)
#pragma unroll
        for (int j = 0; j < 8; j++) acc[i][j] = 0.0f;

    for (int k0 = 0; k0 < K; k0 += 16) {
        // load A tile: 128 rows x 16 cols, store transposed As[k][row]
#pragma unroll
        for (int j = 0; j < 2; j++) {
            int s = tid + j * 256;              // 512 float4 slots
            int r = s >> 2;
            int c4 = (s & 3) << 2;
            int arow = row0 + r;
            float4 v = make_float4(0.f, 0.f, 0.f, 0.f);
            if (arow < M) v = *(const float4*)(A + (size_t)arow * K + k0 + c4);
            As[c4 + 0][r] = v.x;
            As[c4 + 1][r] = v.y;
            As[c4 + 2][r] = v.z;
            As[c4 + 3][r] = v.w;
        }
        // load W tile: 16 rows x 128 cols
#pragma unroll
        for (int j = 0; j < 2; j++) {
            int s = tid + j * 256;
            int kr = s >> 5;
            int c4 = (s & 31) << 2;
            float4 v = *(const float4*)(W + (size_t)(k0 + kr) * 128 + c4);
            *(float4*)&Ws[kr][c4] = v;
        }
        __syncthreads();

#pragma unroll
        for (int kk = 0; kk < 16; kk++) {
            float a[8], b[8];
            *(float4*)&a[0] = *(const float4*)&As[kk][ty * 8];
            *(float4*)&a[4] = *(const float4*)&As[kk][ty * 8 + 4];
            *(float4*)&b[0] = *(const float4*)&Ws[kk][tx * 8];
            *(float4*)&b[4] = *(const float4*)&Ws[kk][tx * 8 + 4];
#pragma unroll
            for (int i = 0; i < 8; i++)
#pragma unroll
                for (int j = 0; j < 8; j++) acc[i][j] += a[i] * b[j];
        }
        __syncthreads();
    }

    float bv[8];
    *(float4*)&bv[0] = *(const float4*)(bias + tx * 8);
    *(float4*)&bv[4] = *(const float4*)(bias + tx * 8 + 4);

#pragma unroll
    for (int i = 0; i < 8; i++) {
        int row = row0 + ty * 8 + i;
        if (row < M) {
            float scale = useDinv ? d_dinv[row] : 1.0f;
            float o[8];
#pragma unroll
            for (int j = 0; j < 8; j++) {
                float v = (acc[i][j] + bv[j]) * scale;
                if (doRelu) v = fmaxf(v, 0.0f);
                o[j] = v;
            }
            *(float4*)(Cc + (size_t)row * 128 + tx * 8)     = *(float4*)&o[0];
            *(float4*)(Cc + (size_t)row * 128 + tx * 8 + 4) = *(float4*)&o[4];
        }
    }
}

// ---------------- CSR aggregation: y[n] = relu(dinv[n]*(g[n] + sum g[src])) ----------------
// one warp per node, 4 floats per lane
__global__ void k_aggregate(const float* __restrict__ g, float* __restrict__ y, int Nn) {
    int t = blockIdx.x * blockDim.x + threadIdx.x;
    int node = t >> 5;
    int lane = t & 31;
    if (node >= Nn) return;

    const float* gl = g + lane * 4;
    float4 acc = *(const float4*)(g + (size_t)node * HID + lane * 4);  // self loop term

    int i = d_off[node];
    int e = d_off[node + 1];
    for (; i + 4 <= e; i += 4) {
        int s0 = d_csr[i], s1 = d_csr[i + 1], s2 = d_csr[i + 2], s3 = d_csr[i + 3];
        float4 v0 = *(const float4*)(gl + (size_t)s0 * HID);
        float4 v1 = *(const float4*)(gl + (size_t)s1 * HID);
        float4 v2 = *(const float4*)(gl + (size_t)s2 * HID);
        float4 v3 = *(const float4*)(gl + (size_t)s3 * HID);
        acc.x += v0.x; acc.y += v0.y; acc.z += v0.z; acc.w += v0.w;
        acc.x += v1.x; acc.y += v1.y; acc.z += v1.z; acc.w += v1.w;
        acc.x += v2.x; acc.y += v2.y; acc.z += v2.z; acc.w += v2.w;
        acc.x += v3.x; acc.y += v3.y; acc.z += v3.z; acc.w += v3.w;
    }
    for (; i < e; i++) {
        int s = d_csr[i];
        float4 v = *(const float4*)(gl + (size_t)s * HID);
        acc.x += v.x; acc.y += v.y; acc.z += v.z; acc.w += v.w;
    }

    float dv = d_dinv[node];
    acc.x = fmaxf(acc.x * dv, 0.0f);
    acc.y = fmaxf(acc.y * dv, 0.0f);
    acc.z = fmaxf(acc.z * dv, 0.0f);
    acc.w = fmaxf(acc.w * dv, 0.0f);
    *(float4*)(y + (size_t)node * HID + lane * 4) = acc;
}

// ---------------- fc3 + log_softmax fused: out[N,64] ----------------
// 256 threads = 4 rows x 64 cols per block
__global__ __launch_bounds__(256) void k_fc3_lsm(
    const float* __restrict__ yin, const float* __restrict__ W,
    const float* __restrict__ b, float* __restrict__ out, int Nn)
{
    __shared__ float Wsh[HID * NCLS];  // 32KB
    __shared__ float ysh[4][HID];
    __shared__ float red[4][NCLS];

    int tid = threadIdx.x;
    for (int i = tid; i < HID * NCLS; i += 256) Wsh[i] = W[i];

    int rr = tid >> 6;
    int c  = tid & 63;
    int row = blockIdx.x * 4 + rr;
    bool valid = row < Nn;

    if (valid) {
        ysh[rr][c]      = yin[(size_t)row * HID + c];
        ysh[rr][c + 64] = yin[(size_t)row * HID + 64 + c];
    } else {
        ysh[rr][c] = 0.0f; ysh[rr][c + 64] = 0.0f;
    }
    __syncthreads();

    float z = b[c];
#pragma unroll 8
    for (int k = 0; k < HID; k++) z += ysh[rr][k] * Wsh[k * NCLS + c];

    // row max
    red[rr][c] = z;
    __syncthreads();
    for (int s = 32; s >= 1; s >>= 1) {
        if (c < s) red[rr][c] = fmaxf(red[rr][c], red[rr][c + s]);
        __syncthreads();
    }
    float m = red[rr][0];
    __syncthreads();

    // sum exp
    red[rr][c] = expf(z - m);
    __syncthreads();
    for (int s = 32; s >= 1; s >>= 1) {
        if (c < s) red[rr][c] += red[rr][c + s];
        __syncthreads();
    }
    float lse = logf(red[rr][0]);

    if (valid) out[(size_t)row * NCLS + c] = z - m - lse;
}

// ---------------- launch ----------------
extern "C" void kernel_launch(void* const* d_in, const int* in_sizes, int n_in,
                              void* d_out, int out_size)
{
    const float* x    = (const float*)d_in[0];
    const int*   ei   = (const int*)d_in[1];
    const float* W0   = (const float*)d_in[2];
    const float* b0   = (const float*)d_in[3];
    const float* W1   = (const float*)d_in[4];
    const float* b1   = (const float*)d_in[5];
    const float* W2   = (const float*)d_in[6];
    const float* b2   = (const float*)d_in[7];
    const float* fc1w = (const float*)d_in[8];
    const float* fc1b = (const float*)d_in[9];
    const float* fc2w = (const float*)d_in[10];
    const float* fc2b = (const float*)d_in[11];
    const float* fc3w = (const float*)d_in[12];
    const float* fc3b = (const float*)d_in[13];
    float* out = (float*)d_out;

    const int N = in_sizes[0] / F_IN;
    const int E = in_sizes[1] / 2;
    const int* src = ei;       // edge_index[0]
    const int* dst = ei + E;   // edge_index[1]

    float *g, *y;
    cudaGetSymbolAddress((void**)&g, d_gbuf);
    cudaGetSymbolAddress((void**)&y, d_ybuf);

    const int T = 256;
    int gN  = (N + T - 1) / T;
    int gE  = (E + T - 1) / T;
    int nb  = (N + 1023) / 1024;
    int gM  = (N + 127) / 128;
    int gAg = (N * 32 + T - 1) / T;
    int gFc = (N + 3) / 4;

    // graph structure: degrees, dinv, CSR
    k_zero<<<gN, T>>>(N);
    k_count<<<gE, T>>>(dst, E);
    k_dinv<<<gN, T>>>(N);
    k_scan1<<<nb, 1024>>>(N);
    k_scan2<<<1, 1>>>(nb);
    k_scan3<<<nb, 1024>>>(N, E);
    k_scatter<<<gE, T>>>(src, dst, E);

    // conv0: g = (x@W0+b0)*dinv ; y = relu(dinv*(g_self + sum g_src))
    k_sgemm<<<gM, T>>>(x, W0, b0, /*dinv*/1, /*relu*/0, g, N, F_IN);
    k_aggregate<<<gAg, T>>>(g, y, N);
    // conv1
    k_sgemm<<<gM, T>>>(y, W1, b1, 1, 0, g, N, HID);
    k_aggregate<<<gAg, T>>>(g, y, N);
    // conv2
    k_sgemm<<<gM, T>>>(y, W2, b2, 1, 0, g, N, HID);
    k_aggregate<<<gAg, T>>>(g, y, N);
    // fc1, fc2
    k_sgemm<<<gM, T>>>(y, fc1w, fc1b, 0, 1, g, N, HID);
    k_sgemm<<<gM, T>>>(g, fc2w, fc2b, 0, 1, y, N, HID);
    // fc3 + log_softmax
    k_fc3_lsm<<<gFc, T>>>(y, fc3w, fc3b, out, N);
}

// round 13
// speedup vs baseline: 1.0773x; 1.0773x over previous
#include <cuda_runtime.h>
#include <cuda_bf16.h>
#include <math.h>
#include <stdint.h>

// Problem constants (shapes fixed by the dataset)
#define F_IN  512
#define HID   128
#define NCLS  64
#define MAX_N 131072
#define MAX_E 2097152

// ---------------- static device scratch (no allocations allowed) ----------------
__device__ __align__(16) float d_gbuf[(size_t)MAX_N * HID];  // 67 MB
__device__ __align__(16) float d_ybuf[(size_t)MAX_N * HID];  // 67 MB
__device__ float d_dinv[MAX_N];
__device__ int   d_deg[MAX_N];
__device__ int   d_off[MAX_N + 1];
__device__ int   d_cur[MAX_N];
__device__ int   d_csr[MAX_E];
__device__ int   d_bsum[256];
__device__ int   d_boff[256];

// ================= PTX helpers (all plain sm_80-era features; no 'a'-arch needed) =================
__device__ __forceinline__ uint32_t smem_u32(const void* p) {
    uint32_t a;
    asm("{ .reg .u64 t; cvta.to.shared.u64 t, %1; cvt.u32.u64 %0, t; }" : "=r"(a) : "l"(p));
    return a;
}

__device__ __forceinline__ void ldm_x4(uint32_t* r, uint32_t addr) {
    asm volatile("ldmatrix.sync.aligned.m8n8.x4.shared.b16 {%0,%1,%2,%3}, [%4];"
        : "=r"(r[0]), "=r"(r[1]), "=r"(r[2]), "=r"(r[3]) : "r"(addr));
}

__device__ __forceinline__ void mma16816(float* d, const uint32_t* a, const uint32_t* b) {
    asm volatile("mma.sync.aligned.m16n8k16.row.col.f32.bf16.bf16.f32 "
        "{%0,%1,%2,%3}, {%4,%5,%6,%7}, {%8,%9}, {%0,%1,%2,%3};"
        : "+f"(d[0]), "+f"(d[1]), "+f"(d[2]), "+f"(d[3])
        : "r"(a[0]), "r"(a[1]), "r"(a[2]), "r"(a[3]), "r"(b[0]), "r"(b[1]));
}

// hi/lo bf16 split of a float pair -> packed bf16x2 words
__device__ __forceinline__ void split2(float a, float b, uint32_t& h, uint32_t& l) {
    __nv_bfloat162 hh = __floats2bfloat162_rn(a, b);
    float ra = a - __low2float(hh);
    float rb = b - __high2float(hh);
    __nv_bfloat162 ll = __floats2bfloat162_rn(ra, rb);
    h = *(uint32_t*)&hh;
    l = *(uint32_t*)&ll;
}

// ---------------- degree / dinv ----------------
__global__ void k_zero(int Nn) {
    int i = blockIdx.x * blockDim.x + threadIdx.x;
    if (i < Nn) { d_deg[i] = 0; d_cur[i] = 0; }
}
__global__ void k_count(const int* __restrict__ dst, int Ee) {
    int i = blockIdx.x * blockDim.x + threadIdx.x;
    if (i < Ee) atomicAdd(&d_deg[dst[i]], 1);
}
__global__ void k_dinv(int Nn) {
    int i = blockIdx.x * blockDim.x + threadIdx.x;
    if (i < Nn) d_dinv[i] = rsqrtf((float)d_deg[i] + 1.0f);  // +1 self loop
}

// ---------------- exclusive scan of d_deg -> d_off ----------------
__global__ void k_scan1(int Nn) {
    __shared__ int sh[1024];
    int t = threadIdx.x;
    int i = blockIdx.x * 1024 + t;
    int v = (i < Nn) ? d_deg[i] : 0;
    sh[t] = v;
    __syncthreads();
    for (int s = 1; s < 1024; s <<= 1) {
        int x = (t >= s) ? sh[t - s] : 0;
        __syncthreads();
        sh[t] += x;
        __syncthreads();
    }
    if (i < Nn) d_off[i] = sh[t] - v;
    if (t == 1023) d_bsum[blockIdx.x] = sh[1023];
}
__global__ void k_scan2(int nb) {
    int run = 0;
    for (int b = 0; b < nb; b++) { d_boff[b] = run; run += d_bsum[b]; }
}
__global__ void k_scan3(int Nn, int Ee) {
    int i = blockIdx.x * 1024 + threadIdx.x;
    if (i < Nn) d_off[i] += d_boff[blockIdx.x];
    if (i == 0) d_off[Nn] = Ee;
}
__global__ void k_scatter(const int* __restrict__ src, const int* __restrict__ dst, int Ee) {
    int i = blockIdx.x * blockDim.x + threadIdx.x;
    if (i < Ee) {
        int d = dst[i];
        int p = d_off[d] + atomicAdd(&d_cur[d], 1);
        d_csr[p] = src[i];
    }
}

// ============ HMMA GEMM: C[M,128] = A[M,K] @ W[K,128] (+b)(*dinv)(relu) ============
// bf16 hi/lo split (hi*hi + hi*lo + lo*hi), fp32 accumulate via mma.sync.m16n8k16.
// CTA tile 128x128, 8 warps (4x2), warp tile 32x64, BK=32, padded smem (80B rows).
#define BK  32
#define AST 40   // halfwords per smem row (32 data + 8 pad); 80B, 16B-aligned rows

__global__ __launch_bounds__(256, 2) void k_gemm_mma(
    const float* __restrict__ A, const float* __restrict__ W,
    const float* __restrict__ bias, int useDinv, int doRelu,
    float* __restrict__ C, int M, int K)
{
    __shared__ __align__(128) __nv_bfloat16 sAh[128 * AST];
    __shared__ __align__(128) __nv_bfloat16 sAl[128 * AST];
    __shared__ __align__(128) __nv_bfloat16 sBh[128 * AST];  // stored [n][k]
    __shared__ __align__(128) __nv_bfloat16 sBl[128 * AST];

    const int tid  = threadIdx.x;
    const int lane = tid & 31;
    const int warp = tid >> 5;
    const int wm = (warp & 3) * 32;    // warp row offset in CTA tile
    const int wn = (warp >> 2) * 64;   // warp col offset
    const int row0 = blockIdx.x * 128;

    const uint32_t uAh = smem_u32(sAh), uAl = smem_u32(sAl);
    const uint32_t uBh = smem_u32(sBh), uBl = smem_u32(sBl);

    // ldmatrix per-thread byte offsets (canonical x4 address patterns)
    const uint32_t aoff = (uint32_t)(((wm + (lane & 15)) * AST + (lane >> 4) * 8) * 2);
    const uint32_t boff = (uint32_t)(((wn + (lane & 7) + ((lane >> 4) & 1) * 8) * AST
                                      + ((lane >> 3) & 1) * 8) * 2);

    float acc[2][8][4];
#pragma unroll
    for (int mb = 0; mb < 2; mb++)
#pragma unroll
        for (int nb = 0; nb < 8; nb++)
#pragma unroll
            for (int q = 0; q < 4; q++) acc[mb][nb][q] = 0.0f;

    for (int k0 = 0; k0 < K; k0 += BK) {
        // ---- A tile: [128 rows x 32 k] fp32 -> hi/lo bf16 ----
#pragma unroll
        for (int j = 0; j < 4; j++) {
            int i = tid + j * 256;              // 1024 float4 slots
            int r = i >> 3;
            int c4 = (i & 7) << 2;
            int gr = row0 + r;
            float4 v = make_float4(0.f, 0.f, 0.f, 0.f);
            if (gr < M) v = *(const float4*)(A + (size_t)gr * K + k0 + c4);
            uint32_t h0, l0, h1, l1;
            split2(v.x, v.y, h0, l0);
            split2(v.z, v.w, h1, l1);
            int o = r * AST + c4;               // even halfword -> 8B-aligned bytes
            *(uint2*)(sAh + o) = make_uint2(h0, h1);
            *(uint2*)(sAl + o) = make_uint2(l0, l1);
        }
        // ---- B tile: sB[n][k] = W[k0+k][n] ----
#pragma unroll
        for (int j = 0; j < 8; j++) {
            int i = tid + j * 256;              // 2048 k-pair slots
            int kk = i >> 7;                    // k pair 0..15
            int n  = i & 127;
            float w0 = W[(size_t)(k0 + 2 * kk)     * 128 + n];
            float w1 = W[(size_t)(k0 + 2 * kk + 1) * 128 + n];
            uint32_t h, l;
            split2(w0, w1, h, l);
            int o = n * AST + 2 * kk;           // even halfword -> 4B-aligned
            *(uint32_t*)(sBh + o) = h;
            *(uint32_t*)(sBl + o) = l;
        }
        __syncthreads();

#pragma unroll
        for (int ks = 0; ks < BK; ks += 16) {
            const uint32_t ksb = (uint32_t)(ks * 2);
            uint32_t ah[2][4], al[2][4], bf[8][2];

            // A_hi frags (two m16 blocks)
            ldm_x4(ah[0], uAh + aoff + ksb);
            ldm_x4(ah[1], uAh + aoff + ksb + 16 * AST * 2);
            // B_hi frags (eight n8 blocks via four x4)
#pragma unroll
            for (int nb4 = 0; nb4 < 4; nb4++) {
                uint32_t r4[4];
                ldm_x4(r4, uBh + boff + ksb + nb4 * 16 * AST * 2);
                bf[2 * nb4][0] = r4[0]; bf[2 * nb4][1] = r4[1];
                bf[2 * nb4 + 1][0] = r4[2]; bf[2 * nb4 + 1][1] = r4[3];
            }
            // hi * hi
#pragma unroll
            for (int mb = 0; mb < 2; mb++)
#pragma unroll
                for (int nb = 0; nb < 8; nb++) mma16816(acc[mb][nb], ah[mb], bf[nb]);

            // A_lo frags, lo * hi (B_hi frags still live)
            ldm_x4(al[0], uAl + aoff + ksb);
            ldm_x4(al[1], uAl + aoff + ksb + 16 * AST * 2);
#pragma unroll
            for (int mb = 0; mb < 2; mb++)
#pragma unroll
                for (int nb = 0; nb < 8; nb++) mma16816(acc[mb][nb], al[mb], bf[nb]);

            // B_lo frags, hi * lo (A_hi frags still live)
#pragma unroll
            for (int nb4 = 0; nb4 < 4; nb4++) {
                uint32_t r4[4];
                ldm_x4(r4, uBl + boff + ksb + nb4 * 16 * AST * 2);
                bf[2 * nb4][0] = r4[0]; bf[2 * nb4][1] = r4[1];
                bf[2 * nb4 + 1][0] = r4[2]; bf[2 * nb4 + 1][1] = r4[3];
            }
#pragma unroll
            for (int mb = 0; mb < 2; mb++)
#pragma unroll
                for (int nb = 0; nb < 8; nb++) mma16816(acc[mb][nb], ah[mb], bf[nb]);
        }
        __syncthreads();
    }

    // ---- epilogue: bias, dinv/relu, write ----
#pragma unroll
    for (int mb = 0; mb < 2; mb++) {
        int r0 = row0 + wm + mb * 16 + (lane >> 2);
        int r1 = r0 + 8;
        float s0 = 1.0f, s1 = 1.0f;
        if (useDinv) {
            if (r0 < M) s0 = d_dinv[r0];
            if (r1 < M) s1 = d_dinv[r1];
        }
#pragma unroll
        for (int nb = 0; nb < 8; nb++) {
            int c = wn + nb * 8 + (lane & 3) * 2;
            float2 bv = *(const float2*)(bias + c);
            float v0 = (acc[mb][nb][0] + bv.x) * s0;
            float v1 = (acc[mb][nb][1] + bv.y) * s0;
            float v2 = (acc[mb][nb][2] + bv.x) * s1;
            float v3 = (acc[mb][nb][3] + bv.y) * s1;
            if (doRelu) {
                v0 = fmaxf(v0, 0.f); v1 = fmaxf(v1, 0.f);
                v2 = fmaxf(v2, 0.f); v3 = fmaxf(v3, 0.f);
            }
            if (r0 < M) *(float2*)(C + (size_t)r0 * 128 + c) = make_float2(v0, v1);
            if (r1 < M) *(float2*)(C + (size_t)r1 * 128 + c) = make_float2(v2, v3);
        }
    }
}

// ---------------- CSR aggregation: y[n] = relu(dinv[n]*(g[n] + sum g[src])) ----------------
__global__ void k_aggregate(const float* __restrict__ g, float* __restrict__ y, int Nn) {
    int t = blockIdx.x * blockDim.x + threadIdx.x;
    int node = t >> 5;
    int lane = t & 31;
    if (node >= Nn) return;

    const float* gl = g + lane * 4;
    float4 acc = *(const float4*)(g + (size_t)node * HID + lane * 4);  // self loop term

    int i = d_off[node];
    int e = d_off[node + 1];
    for (; i + 4 <= e; i += 4) {
        int s0 = d_csr[i], s1 = d_csr[i + 1], s2 = d_csr[i + 2], s3 = d_csr[i + 3];
        float4 v0 = *(const float4*)(gl + (size_t)s0 * HID);
        float4 v1 = *(const float4*)(gl + (size_t)s1 * HID);
        float4 v2 = *(const float4*)(gl + (size_t)s2 * HID);
        float4 v3 = *(const float4*)(gl + (size_t)s3 * HID);
        acc.x += v0.x; acc.y += v0.y; acc.z += v0.z; acc.w += v0.w;
        acc.x += v1.x; acc.y += v1.y; acc.z += v1.z; acc.w += v1.w;
        acc.x += v2.x; acc.y += v2.y; acc.z += v2.z; acc.w += v2.w;
        acc.x += v3.x; acc.y += v3.y; acc.z += v3.z; acc.w += v3.w;
    }
    for (; i < e; i++) {
        int s = d_csr[i];
        float4 v = *(const float4*)(gl + (size_t)s * HID);
        acc.x += v.x; acc.y += v.y; acc.z += v.z; acc.w += v.w;
    }

    float dv = d_dinv[node];
    acc.x = fmaxf(acc.x * dv, 0.0f);
    acc.y = fmaxf(acc.y * dv, 0.0f);
    acc.z = fmaxf(acc.z * dv, 0.0f);
    acc.w = fmaxf(acc.w * dv, 0.0f);
    *(float4*)(y + (size_t)node * HID + lane * 4) = acc;
}

// ---------------- fc3 + log_softmax fused ----------------
__global__ __launch_bounds__(256) void k_fc3_lsm(
    const float* __restrict__ yin, const float* __restrict__ W,
    const float* __restrict__ b, float* __restrict__ out, int Nn)
{
    __shared__ float Wsh[HID * NCLS];
    __shared__ float ysh[4][HID];
    __shared__ float red[4][NCLS];

    int tid = threadIdx.x;
    for (int i = tid; i < HID * NCLS; i += 256) Wsh[i] = W[i];

    int rr = tid >> 6;
    int c  = tid & 63;
    int row = blockIdx.x * 4 + rr;
    bool valid = row < Nn;

    if (valid) {
        ysh[rr][c]      = yin[(size_t)row * HID + c];
        ysh[rr][c + 64] = yin[(size_t)row * HID + 64 + c];
    } else {
        ysh[rr][c] = 0.0f; ysh[rr][c + 64] = 0.0f;
    }
    __syncthreads();

    float z = b[c];
#pragma unroll 8
    for (int k = 0; k < HID; k++) z += ysh[rr][k] * Wsh[k * NCLS + c];

    red[rr][c] = z;
    __syncthreads();
    for (int s = 32; s >= 1; s >>= 1) {
        if (c < s) red[rr][c] = fmaxf(red[rr][c], red[rr][c + s]);
        __syncthreads();
    }
    float m = red[rr][0];
    __syncthreads();

    red[rr][c] = expf(z - m);
    __syncthreads();
    for (int s = 32; s >= 1; s >>= 1) {
        if (c < s) red[rr][c] += red[rr][c + s];
        __syncthreads();
    }
    float lse = logf(red[rr][0]);

    if (valid) out[(size_t)row * NCLS + c] = z - m - lse;
}

// ---------------- launch ----------------
extern "C" void kernel_launch(void* const* d_in, const int* in_sizes, int n_in,
                              void* d_out, int out_size)
{
    const float* x    = (const float*)d_in[0];
    const int*   ei   = (const int*)d_in[1];
    const float* W0   = (const float*)d_in[2];
    const float* b0   = (const float*)d_in[3];
    const float* W1   = (const float*)d_in[4];
    const float* b1   = (const float*)d_in[5];
    const float* W2   = (const float*)d_in[6];
    const float* b2   = (const float*)d_in[7];
    const float* fc1w = (const float*)d_in[8];
    const float* fc1b = (const float*)d_in[9];
    const float* fc2w = (const float*)d_in[10];
    const float* fc2b = (const float*)d_in[11];
    const float* fc3w = (const float*)d_in[12];
    const float* fc3b = (const float*)d_in[13];
    float* out = (float*)d_out;

    const int N = in_sizes[0] / F_IN;
    const int E = in_sizes[1] / 2;
    const int* src = ei;       // edge_index[0]
    const int* dst = ei + E;   // edge_index[1]

    float *g, *y;
    cudaGetSymbolAddress((void**)&g, d_gbuf);
    cudaGetSymbolAddress((void**)&y, d_ybuf);

    const int T = 256;
    int gN  = (N + T - 1) / T;
    int gE  = (E + T - 1) / T;
    int nb  = (N + 1023) / 1024;
    int gM  = (N + 127) / 128;
    int gAg = (N * 32 + T - 1) / T;
    int gFc = (N + 3) / 4;

    // graph structure: degrees, dinv, CSR
    k_zero<<<gN, T>>>(N);
    k_count<<<gE, T>>>(dst, E);
    k_dinv<<<gN, T>>>(N);
    k_scan1<<<nb, 1024>>>(N);
    k_scan2<<<1, 1>>>(nb);
    k_scan3<<<nb, 1024>>>(N, E);
    k_scatter<<<gE, T>>>(src, dst, E);

    // conv0: g = (x@W0+b0)*dinv ; y = relu(dinv*(g_self + sum g_src))
    k_gemm_mma<<<gM, T>>>(x, W0, b0, 1, 0, g, N, F_IN);
    k_aggregate<<<gAg, T>>>(g, y, N);
    // conv1
    k_gemm_mma<<<gM, T>>>(y, W1, b1, 1, 0, g, N, HID);
    k_aggregate<<<gAg, T>>>(g, y, N);
    // conv2
    k_gemm_mma<<<gM, T>>>(y, W2, b2, 1, 0, g, N, HID);
    k_aggregate<<<gAg, T>>>(g, y, N);
    // fc1, fc2
    k_gemm_mma<<<gM, T>>>(y, fc1w, fc1b, 0, 1, g, N, HID);
    k_gemm_mma<<<gM, T>>>(g, fc2w, fc2b, 0, 1, y, N, HID);
    // fc3 + log_softmax
    k_fc3_lsm<<<gFc, T>>>(y, fc3w, fc3b, out, N);
}